// round 1
// baseline (speedup 1.0000x reference)
#include <cuda_runtime.h>
#include <math.h>
#include <stdint.h>

#define CC 8   // cin chunk

// ---------------- scratch activations (alloc-free rule: __device__ globals) ----
__device__ float g_h0[16u*128u*128u*128u];   // enc0 out: 33.5M
__device__ float g_h1[16u*256u*64u*64u];     // enc1 out: 16.8M
__device__ float g_h2[16u*512u*32u*32u];     // enc2 out:  8.4M
__device__ float g_d0[16u*512u*64u*64u];     // dec0 out: 33.5M
__device__ float g_d1[16u*256u*128u*128u];   // dec1 out: 67.1M
__device__ float g_d2[16u*128u*256u*256u];   // dec2 out: 134.2M

// ---------------- swizzled weight smem helpers: layout [row=cin*16+tap][64 couts]
__device__ __forceinline__ void stw(float* sw, int row, int co, float v) {
    sw[row * 64 + (co ^ ((row & 15) << 2))] = v;
}
__device__ __forceinline__ float4 ldw4(const float* sw, int row, int cg4) {
    return *reinterpret_cast<const float4*>(sw + row * 64 + (cg4 ^ ((row & 15) << 2)));
}

// =====================================================================
// Conv2d k=4 s=2 p=1 (+bias, optional ReLU). NCHW.
// Block: 64 couts x 8x8 outputs. 128 threads = 16 cout-groups x 8 row-groups.
// =====================================================================
__global__ void __launch_bounds__(128) conv4s2(
    const float* __restrict__ in, const float* __restrict__ w,
    const float* __restrict__ bias, float* __restrict__ out,
    int Cin, int Cout, int Hin, int Win, int Hout, int Wout, int relu)
{
    __shared__ float s_in[CC][18][18];
    __shared__ float s_w[CC * 16 * 64];

    int coutTiles = Cout >> 6;
    int n     = blockIdx.z / coutTiles;
    int cout0 = (blockIdx.z % coutTiles) << 6;
    int oy0 = blockIdx.y << 3, ox0 = blockIdx.x << 3;
    int tid = threadIdx.x;
    int pg = tid & 7;          // output row within tile
    int cg4 = (tid >> 3) << 2; // first of 4 couts

    float acc[4][8];
    #pragma unroll
    for (int j = 0; j < 4; j++) {
        float b = bias[cout0 + cg4 + j];
        #pragma unroll
        for (int q = 0; q < 8; q++) acc[j][q] = b;
    }

    size_t HW = (size_t)Hin * Win;
    const float* in_n = in + (size_t)n * Cin * HW;
    int iy0 = oy0 * 2 - 1, ix0 = ox0 * 2 - 1;

    #pragma unroll 1
    for (int c0 = 0; c0 < Cin; c0 += CC) {
        // ---- stage input tile (zero-padded) ----
        for (int r = tid; r < CC * 18; r += 128) {
            int cl = r / 18, ry = r - cl * 18;
            int c = c0 + cl, gy = iy0 + ry;
            bool rowok = (c < Cin) && (gy >= 0) && (gy < Hin);
            const float* src = in_n + (size_t)c * HW + (size_t)gy * Win;
            #pragma unroll
            for (int rx = 0; rx < 18; rx++) {
                int gx = ix0 + rx;
                s_in[cl][ry][rx] = (rowok && gx >= 0 && gx < Win) ? src[gx] : 0.f;
            }
        }
        // ---- stage weights: OIHW gather, tap-fastest for coalescing ----
        for (int i = tid; i < CC * 16 * 64; i += 128) {
            int tap = i & 15, cl = (i >> 4) & (CC - 1), co = i >> 7;
            int c = c0 + cl;
            float v = (c < Cin) ? w[((size_t)(cout0 + co) * Cin + c) * 16 + tap] : 0.f;
            stw(s_w, cl * 16 + tap, co, v);
        }
        __syncthreads();

        #pragma unroll 1
        for (int cl = 0; cl < CC; cl++) {
            #pragma unroll
            for (int kh = 0; kh < 4; kh++) {
                #pragma unroll
                for (int kw = 0; kw < 4; kw++) {
                    float iv[8];
                    #pragma unroll
                    for (int q = 0; q < 8; q++) iv[q] = s_in[cl][2 * pg + kh][2 * q + kw];
                    float4 wv = ldw4(s_w, cl * 16 + kh * 4 + kw, cg4);
                    #pragma unroll
                    for (int q = 0; q < 8; q++) {
                        acc[0][q] = fmaf(wv.x, iv[q], acc[0][q]);
                        acc[1][q] = fmaf(wv.y, iv[q], acc[1][q]);
                        acc[2][q] = fmaf(wv.z, iv[q], acc[2][q]);
                        acc[3][q] = fmaf(wv.w, iv[q], acc[3][q]);
                    }
                }
            }
        }
        __syncthreads();
    }

    size_t HWo = (size_t)Hout * Wout;
    float* out_p = out + (size_t)n * Cout * HWo + (size_t)(oy0 + pg) * Wout + ox0;
    #pragma unroll
    for (int j = 0; j < 4; j++) {
        float v[8];
        #pragma unroll
        for (int q = 0; q < 8; q++) {
            v[q] = acc[j][q];
            if (relu) v[q] = fmaxf(v[q], 0.f);
        }
        float* p = out_p + (size_t)(cout0 + cg4 + j) * HWo;
        *(float4*)p       = make_float4(v[0], v[1], v[2], v[3]);
        *(float4*)(p + 4) = make_float4(v[4], v[5], v[6], v[7]);
    }
}

// =====================================================================
// ConvTranspose2d semantics of lax.conv_transpose(k=4, s=2, 'SAME',
// transpose_kernel=False): lhs-dilated (x2) cross-correlation, pad (2,2).
// Per output (p,q): h=(p>>1)+(p&1)+a-1, kh=(p&1)+2a, a,b in {0,1}.
// =====================================================================
#define CTAP(q, wv, ivv)                              \
    acc[0][q] = fmaf((wv).x, (ivv), acc[0][q]);       \
    acc[1][q] = fmaf((wv).y, (ivv), acc[1][q]);       \
    acc[2][q] = fmaf((wv).z, (ivv), acc[2][q]);       \
    acc[3][q] = fmaf((wv).w, (ivv), acc[3][q]);

__global__ void __launch_bounds__(128) convT4s2(
    const float* __restrict__ in, const float* __restrict__ w,
    const float* __restrict__ bias, float* __restrict__ out,
    int Cin, int Cout, int Hin, int Win, int relu)
{
    __shared__ float s_in[CC][6][6];
    __shared__ float s_w[CC * 16 * 64];

    int Hout = Hin * 2, Wout = Win * 2;
    int coutTiles = Cout >> 6;
    int n     = blockIdx.z / coutTiles;
    int cout0 = (blockIdx.z % coutTiles) << 6;
    int oy0 = blockIdx.y << 3, ox0 = blockIdx.x << 3;
    int tid = threadIdx.x;
    int pg = tid & 7;
    int cg4 = (tid >> 3) << 2;

    float acc[4][8];
    #pragma unroll
    for (int j = 0; j < 4; j++) {
        float b = bias[cout0 + cg4 + j];
        #pragma unroll
        for (int q = 0; q < 8; q++) acc[j][q] = b;
    }

    size_t HW = (size_t)Hin * Win;
    const float* in_n = in + (size_t)n * Cin * HW;
    int hbase = (oy0 >> 1) - 1, wbase = (ox0 >> 1) - 1;
    int rp = pg & 1;
    int lh0 = (pg >> 1) + rp;  // local input row = lh0 + a

    #pragma unroll 1
    for (int c0 = 0; c0 < Cin; c0 += CC) {
        for (int r = tid; r < CC * 6; r += 128) {
            int cl = r / 6, ry = r - cl * 6;
            int c = c0 + cl, gy = hbase + ry;
            bool rowok = (c < Cin) && (gy >= 0) && (gy < Hin);
            const float* src = in_n + (size_t)c * HW + (size_t)gy * Win;
            #pragma unroll
            for (int rx = 0; rx < 6; rx++) {
                int gx = wbase + rx;
                s_in[cl][ry][rx] = (rowok && gx >= 0 && gx < Win) ? src[gx] : 0.f;
            }
        }
        for (int i = tid; i < CC * 16 * 64; i += 128) {
            int tap = i & 15, cl = (i >> 4) & (CC - 1), co = i >> 7;
            int c = c0 + cl;
            float v = (c < Cin) ? w[((size_t)(cout0 + co) * Cin + c) * 16 + tap] : 0.f;
            stw(s_w, cl * 16 + tap, co, v);
        }
        __syncthreads();

        #pragma unroll 1
        for (int cl = 0; cl < CC; cl++) {
            #pragma unroll
            for (int a = 0; a < 2; a++) {
                int lh = lh0 + a;
                int khrow = cl * 16 + (rp + 2 * a) * 4;
                #pragma unroll
                for (int b = 0; b < 2; b++) {
                    float i0 = s_in[cl][lh][b + 0];
                    float i1 = s_in[cl][lh][b + 1];
                    float i2 = s_in[cl][lh][b + 2];
                    float i3 = s_in[cl][lh][b + 3];
                    float i4 = s_in[cl][lh][b + 4];
                    float4 we = ldw4(s_w, khrow + 2 * b, cg4);      // kw = 2b   (even q)
                    float4 wo = ldw4(s_w, khrow + 2 * b + 1, cg4);  // kw = 2b+1 (odd q)
                    CTAP(0, we, i0) CTAP(1, wo, i1) CTAP(2, we, i1) CTAP(3, wo, i2)
                    CTAP(4, we, i2) CTAP(5, wo, i3) CTAP(6, we, i3) CTAP(7, wo, i4)
                }
            }
        }
        __syncthreads();
    }

    size_t HWo = (size_t)Hout * Wout;
    float* out_p = out + (size_t)n * Cout * HWo + (size_t)(oy0 + pg) * Wout + ox0;
    #pragma unroll
    for (int j = 0; j < 4; j++) {
        float v[8];
        #pragma unroll
        for (int q = 0; q < 8; q++) {
            v[q] = acc[j][q];
            if (relu) v[q] = fmaxf(v[q], 0.f);
        }
        float* p = out_p + (size_t)(cout0 + cg4 + j) * HWo;
        *(float4*)p       = make_float4(v[0], v[1], v[2], v[3]);
        *(float4*)(p + 4) = make_float4(v[4], v[5], v[6], v[7]);
    }
}

// =====================================================================
// 1x1 conv (proj): Cout=64 tile, 64 pixels per block.
// =====================================================================
__global__ void __launch_bounds__(128) conv1x1(
    const float* __restrict__ in, const float* __restrict__ w,
    const float* __restrict__ bias, float* __restrict__ out,
    int Cin, int Cout, int HW)
{
    __shared__ float s_in[CC * 64];
    __shared__ float s_w[CC * 64];
    int n = blockIdx.y;
    int hw0 = blockIdx.x * 64;
    int tid = threadIdx.x, pg = tid & 7, cg4 = (tid >> 3) << 2;

    float acc[4][8];
    #pragma unroll
    for (int j = 0; j < 4; j++) {
        float b = bias[cg4 + j];
        #pragma unroll
        for (int q = 0; q < 8; q++) acc[j][q] = b;
    }

    #pragma unroll 1
    for (int c0 = 0; c0 < Cin; c0 += CC) {
        for (int i = tid; i < CC * 64; i += 128) {
            int cl = i >> 6, px = i & 63;
            s_in[cl * 64 + px] = in[((size_t)n * Cin + c0 + cl) * HW + hw0 + px];
        }
        for (int i = tid; i < CC * 64; i += 128) {
            int cl = i & 7, co = i >> 3;
            stw(s_w, cl, co, w[(size_t)co * Cin + c0 + cl]);
        }
        __syncthreads();
        #pragma unroll
        for (int cl = 0; cl < CC; cl++) {
            float4 wv = ldw4(s_w, cl, cg4);
            #pragma unroll
            for (int q = 0; q < 8; q++) {
                float iv = s_in[cl * 64 + pg * 8 + q];
                acc[0][q] = fmaf(wv.x, iv, acc[0][q]);
                acc[1][q] = fmaf(wv.y, iv, acc[1][q]);
                acc[2][q] = fmaf(wv.z, iv, acc[2][q]);
                acc[3][q] = fmaf(wv.w, iv, acc[3][q]);
            }
        }
        __syncthreads();
    }
    #pragma unroll
    for (int j = 0; j < 4; j++) {
        float* p = out + ((size_t)n * Cout + cg4 + j) * HW + hw0 + pg * 8;
        *(float4*)p       = make_float4(acc[j][0], acc[j][1], acc[j][2], acc[j][3]);
        *(float4*)(p + 4) = make_float4(acc[j][4], acc[j][5], acc[j][6], acc[j][7]);
    }
}

// =====================================================================
// VQ: per (n,h,w) row of z (D=64), argmin over K=1024 codes of |c|^2-2 z.c
// (monotone-equivalent to squared distance). Writes z_q gather.
// =====================================================================
__global__ void __launch_bounds__(128) vq_kernel(
    const float* __restrict__ z, const float* __restrict__ cb, float* __restrict__ zq)
{
    __shared__ float4 s_cb[128 * 16];  // 128 codes x 64 floats
    int row = blockIdx.x * 128 + threadIdx.x;  // 16384 rows total
    int n = row >> 10, hw = row & 1023;
    const float* zp = z + (size_t)n * 64 * 1024 + hw;
    float4 zv[16];
    #pragma unroll
    for (int j = 0; j < 16; j++)
        zv[j] = make_float4(zp[(4 * j + 0) * 1024], zp[(4 * j + 1) * 1024],
                            zp[(4 * j + 2) * 1024], zp[(4 * j + 3) * 1024]);

    float best = 3.4e38f;
    int bidx = 0;
    #pragma unroll 1
    for (int k0 = 0; k0 < 1024; k0 += 128) {
        __syncthreads();
        const float4* cbv = (const float4*)cb + (size_t)k0 * 16;
        for (int i = threadIdx.x; i < 128 * 16; i += 128) s_cb[i] = cbv[i];
        __syncthreads();
        #pragma unroll 1
        for (int k = 0; k < 128; k++) {
            float d0 = 0.f, d1 = 0.f, d2 = 0.f, d3 = 0.f;
            #pragma unroll
            for (int j = 0; j < 16; j++) {
                float4 c = s_cb[k * 16 + j];
                float4 zz = zv[j];
                d0 = fmaf(c.x, fmaf(-2.f, zz.x, c.x), d0);
                d1 = fmaf(c.y, fmaf(-2.f, zz.y, c.y), d1);
                d2 = fmaf(c.z, fmaf(-2.f, zz.z, c.z), d2);
                d3 = fmaf(c.w, fmaf(-2.f, zz.w, c.w), d3);
            }
            float dist = (d0 + d1) + (d2 + d3);
            if (dist < best) { best = dist; bidx = k0 + k; }
        }
    }
    const float4* crow = (const float4*)(cb + (size_t)bidx * 64);
    float* qp = zq + (size_t)n * 64 * 1024 + hw;
    #pragma unroll
    for (int j = 0; j < 16; j++) {
        float4 c = crow[j];
        qp[(4 * j + 0) * 1024] = c.x; qp[(4 * j + 1) * 1024] = c.y;
        qp[(4 * j + 2) * 1024] = c.z; qp[(4 * j + 3) * 1024] = c.w;
    }
}

// =====================================================================
// 3x3 s1 p1 output conv, Cout=3 (no relu).
// Block: 16x16 pixels, 256 threads; each thread accumulates 3 couts.
// =====================================================================
__global__ void __launch_bounds__(256) conv3x3_out(
    const float* __restrict__ in, const float* __restrict__ w,
    const float* __restrict__ bias, float* __restrict__ out,
    int Cin, int H, int W)
{
    __shared__ float s_in[16][18][18];
    __shared__ float s_w3[3 * 128 * 9];
    int n = blockIdx.z;
    int ty = blockIdx.y * 16, tx = blockIdx.x * 16;
    int tid = threadIdx.x, px = tid & 15, py = tid >> 4;

    for (int i = tid; i < 3 * Cin * 9; i += 256) s_w3[i] = w[i];

    float a0 = bias[0], a1 = bias[1], a2 = bias[2];
    size_t HW = (size_t)H * W;
    const float* in_n = in + (size_t)n * Cin * HW;

    #pragma unroll 1
    for (int c0 = 0; c0 < Cin; c0 += 16) {
        __syncthreads();
        for (int r = tid; r < 16 * 18; r += 256) {
            int cl = r / 18, ry = r - cl * 18;
            int c = c0 + cl, gy = ty - 1 + ry;
            bool rowok = (gy >= 0) && (gy < H);
            const float* src = in_n + (size_t)c * HW + (size_t)gy * W;
            #pragma unroll
            for (int rx = 0; rx < 18; rx++) {
                int gx = tx - 1 + rx;
                s_in[cl][ry][rx] = (rowok && gx >= 0 && gx < W) ? src[gx] : 0.f;
            }
        }
        __syncthreads();
        #pragma unroll 1
        for (int cl = 0; cl < 16; cl++) {
            int c = c0 + cl;
            float w0[9], w1[9], w2[9];
            #pragma unroll
            for (int t = 0; t < 9; t++) {
                w0[t] = s_w3[(0 * Cin + c) * 9 + t];
                w1[t] = s_w3[(1 * Cin + c) * 9 + t];
                w2[t] = s_w3[(2 * Cin + c) * 9 + t];
            }
            #pragma unroll
            for (int kh = 0; kh < 3; kh++)
                #pragma unroll
                for (int kw = 0; kw < 3; kw++) {
                    float iv = s_in[cl][py + kh][px + kw];
                    a0 = fmaf(w0[kh * 3 + kw], iv, a0);
                    a1 = fmaf(w1[kh * 3 + kw], iv, a1);
                    a2 = fmaf(w2[kh * 3 + kw], iv, a2);
                }
        }
    }
    size_t o = (size_t)n * 3 * HW + (size_t)(ty + py) * W + tx + px;
    out[o] = a0; out[o + HW] = a1; out[o + 2 * HW] = a2;
}

// =====================================================================
extern "C" void kernel_launch(void* const* d_in, const int* in_sizes, int n_in,
                              void* d_out, int out_size)
{
    const float* x       = (const float*)d_in[0];
    const float* enc_w0  = (const float*)d_in[1];
    const float* enc_b0  = (const float*)d_in[2];
    const float* enc_w1  = (const float*)d_in[3];
    const float* enc_b1  = (const float*)d_in[4];
    const float* enc_w2  = (const float*)d_in[5];
    const float* enc_b2  = (const float*)d_in[6];
    const float* proj_w  = (const float*)d_in[7];
    const float* proj_b  = (const float*)d_in[8];
    const float* dec_w0  = (const float*)d_in[9];
    const float* dec_b0  = (const float*)d_in[10];
    const float* dec_w1  = (const float*)d_in[11];
    const float* dec_b1  = (const float*)d_in[12];
    const float* dec_w2  = (const float*)d_in[13];
    const float* dec_b2  = (const float*)d_in[14];
    const float* out_w   = (const float*)d_in[15];
    const float* out_b   = (const float*)d_in[16];
    const float* codebook= (const float*)d_in[17];

    float *h0, *h1, *h2, *d0, *d1, *d2;
    cudaGetSymbolAddress((void**)&h0, g_h0);
    cudaGetSymbolAddress((void**)&h1, g_h1);
    cudaGetSymbolAddress((void**)&h2, g_h2);
    cudaGetSymbolAddress((void**)&d0, g_d0);
    cudaGetSymbolAddress((void**)&d1, g_d1);
    cudaGetSymbolAddress((void**)&d2, g_d2);

    float* out   = (float*)d_out;
    float* recon = out;                          // 16*3*256*256 = 3145728
    float* z     = out + 3145728;                // 16*64*32*32  = 1048576
    float* zq    = z + 1048576;                  // 16*64*32*32  = 1048576

    // encoder
    conv4s2<<<dim3(16, 16, 16 * 2), 128>>>(x,  enc_w0, enc_b0, h0, 3,   128, 256, 256, 128, 128, 1);
    conv4s2<<<dim3(8,  8,  16 * 4), 128>>>(h0, enc_w1, enc_b1, h1, 128, 256, 128, 128, 64,  64,  1);
    conv4s2<<<dim3(4,  4,  16 * 8), 128>>>(h1, enc_w2, enc_b2, h2, 256, 512, 64,  64,  32,  32,  1);
    // proj -> z (written straight into d_out)
    conv1x1<<<dim3(16, 16), 128>>>(h2, proj_w, proj_b, z, 512, 64, 1024);
    // quantize -> z_q (into d_out)
    vq_kernel<<<128, 128>>>(z, codebook, zq);
    // decoder (z_q_st == z_q numerically up to O(eps*|z|), negligible here)
    convT4s2<<<dim3(8,  8,  16 * 8), 128>>>(zq, dec_w0, dec_b0, d0, 64,  512, 32,  32,  1);
    convT4s2<<<dim3(16, 16, 16 * 4), 128>>>(d0, dec_w1, dec_b1, d1, 512, 256, 64,  64,  1);
    convT4s2<<<dim3(32, 32, 16 * 2), 128>>>(d1, dec_w2, dec_b2, d2, 256, 128, 128, 128, 1);
    // output conv -> recon
    conv3x3_out<<<dim3(16, 16, 16), 256>>>(d2, out_w, out_b, recon, 128, 256, 256);
}

// round 3
// speedup vs baseline: 1.7071x; 1.7071x over previous
#include <cuda_runtime.h>
#include <math.h>
#include <stdint.h>

#define CC 8   // cin chunk
typedef unsigned long long ull;

// ---------------- packed f32x2 helpers (Blackwell FFMA2 path) ----------------
__device__ __forceinline__ ull pack2(float lo, float hi) {
    ull r; asm("mov.b64 %0, {%1, %2};" : "=l"(r) : "f"(lo), "f"(hi)); return r;
}
__device__ __forceinline__ ull splat2(float v) { return pack2(v, v); }
__device__ __forceinline__ void fma2(ull& d, ull a, ull b) {
    asm("fma.rn.f32x2 %0, %1, %2, %0;" : "+l"(d) : "l"(a), "l"(b));
}
__device__ __forceinline__ float2 unpack2(ull v) {
    float2 f; asm("mov.b64 {%0, %1}, %2;" : "=f"(f.x), "=f"(f.y) : "l"(v)); return f;
}

// ---------------- scratch activations (alloc-free rule: __device__ globals) ----
__device__ float g_h0[16u*128u*128u*128u];   // enc0 out
__device__ float g_h1[16u*256u*64u*64u];     // enc1 out
__device__ float g_h2[16u*512u*32u*32u];     // enc2 out
__device__ float g_d0[16u*512u*64u*64u];     // dec0 out
__device__ float g_d1[16u*256u*128u*128u];   // dec1 out
__device__ float g_d2[16u*128u*256u*256u];   // dec2 out

// ---------------- swizzled weight smem: layout [row=cin*16+tap][64 couts]
__device__ __forceinline__ void stw(float* sw, int row, int co, float v) {
    sw[row * 64 + (co ^ ((row & 15) << 2))] = v;
}
__device__ __forceinline__ void ldw2x2(const float* sw, int row, int cg4, ull& w01, ull& w23) {
    float4 v = *reinterpret_cast<const float4*>(sw + row * 64 + (cg4 ^ ((row & 15) << 2)));
    w01 = pack2(v.x, v.y);
    w23 = pack2(v.z, v.w);
}

// =====================================================================
// Conv2d k=4 s=2 p=1 (+bias, optional ReLU). NCHW. f32x2 packed FMA.
// Block: 64 couts x 8x8 outputs. 128 threads = 16 cout-groups x 8 rows.
// =====================================================================
__global__ void __launch_bounds__(128, 4) conv4s2(
    const float* __restrict__ in, const float* __restrict__ w,
    const float* __restrict__ bias, float* __restrict__ out,
    int Cin, int Cout, int Hin, int Win, int Hout, int Wout, int relu)
{
    __shared__ float s_in[CC][18][18];
    __shared__ float s_w[CC * 16 * 64];

    int coutTiles = Cout >> 6;
    int n     = blockIdx.z / coutTiles;
    int cout0 = (blockIdx.z % coutTiles) << 6;
    int oy0 = blockIdx.y << 3, ox0 = blockIdx.x << 3;
    int tid = threadIdx.x;
    int pg = tid & 7;          // output row within tile
    int cg4 = (tid >> 3) << 2; // first of 4 couts

    ull acc2[2][8];            // [cout-pair][pixel]
    {
        ull b01 = pack2(bias[cout0 + cg4 + 0], bias[cout0 + cg4 + 1]);
        ull b23 = pack2(bias[cout0 + cg4 + 2], bias[cout0 + cg4 + 3]);
        #pragma unroll
        for (int q = 0; q < 8; q++) { acc2[0][q] = b01; acc2[1][q] = b23; }
    }

    size_t HW = (size_t)Hin * Win;
    const float* in_n = in + (size_t)n * Cin * HW;
    int iy0 = oy0 * 2 - 1, ix0 = ox0 * 2 - 1;

    #pragma unroll 1
    for (int c0 = 0; c0 < Cin; c0 += CC) {
        // ---- stage input tile (zero-padded), coalesced flattened ----
        for (int i = tid; i < CC * 18 * 18; i += 128) {
            int cl = i / 324, rem = i - cl * 324;
            int ry = rem / 18, rx = rem - ry * 18;
            int c = c0 + cl, gy = iy0 + ry, gx = ix0 + rx;
            bool ok = (c < Cin) && (gy >= 0) && (gy < Hin) && (gx >= 0) && (gx < Win);
            s_in[cl][ry][rx] = ok ? in_n[(size_t)c * HW + (size_t)gy * Win + gx] : 0.f;
        }
        // ---- stage weights: OIHW gather, tap-fastest for coalescing ----
        for (int i = tid; i < CC * 16 * 64; i += 128) {
            int tap = i & 15, cl = (i >> 4) & (CC - 1), co = i >> 7;
            int c = c0 + cl;
            float v = (c < Cin) ? w[((size_t)(cout0 + co) * Cin + c) * 16 + tap] : 0.f;
            stw(s_w, cl * 16 + tap, co, v);
        }
        __syncthreads();

        #pragma unroll 1
        for (int cl = 0; cl < CC; cl++) {
            #pragma unroll
            for (int kh = 0; kh < 4; kh++) {
                const float* row = &s_in[cl][2 * pg + kh][0];
                ull iv[18];
                #pragma unroll
                for (int rx = 0; rx < 18; rx++) iv[rx] = splat2(row[rx]);
                #pragma unroll
                for (int kw = 0; kw < 4; kw++) {
                    ull w01, w23;
                    ldw2x2(s_w, cl * 16 + kh * 4 + kw, cg4, w01, w23);
                    #pragma unroll
                    for (int q = 0; q < 8; q++) {
                        ull s = iv[2 * q + kw];
                        fma2(acc2[0][q], w01, s);
                        fma2(acc2[1][q], w23, s);
                    }
                }
            }
        }
        __syncthreads();
    }

    size_t HWo = (size_t)Hout * Wout;
    float* out_p = out + (size_t)n * Cout * HWo + (size_t)(oy0 + pg) * Wout + ox0;
    float v[4][8];
    #pragma unroll
    for (int jp = 0; jp < 2; jp++)
        #pragma unroll
        for (int q = 0; q < 8; q++) {
            float2 f = unpack2(acc2[jp][q]);
            v[2 * jp][q] = relu ? fmaxf(f.x, 0.f) : f.x;
            v[2 * jp + 1][q] = relu ? fmaxf(f.y, 0.f) : f.y;
        }
    #pragma unroll
    for (int j = 0; j < 4; j++) {
        float* p = out_p + (size_t)(cout0 + cg4 + j) * HWo;
        *(float4*)p       = make_float4(v[j][0], v[j][1], v[j][2], v[j][3]);
        *(float4*)(p + 4) = make_float4(v[j][4], v[j][5], v[j][6], v[j][7]);
    }
}

// =====================================================================
// ConvTranspose2d (lax.conv_transpose k=4 s=2 SAME, transpose_kernel=False):
// lhs-dilated x2 cross-correlation, pad (2,2).
// Per output (P,Q): in row h=(P>>1)+(P&1)+a-1, kh=(P&1)+2a (a,b in {0,1}).
// Block: 64 couts x 16x16 outputs, 256 threads. Thread: 4 couts x 16 cols.
// =====================================================================
__global__ void __launch_bounds__(256, 2) convT4s2(
    const float* __restrict__ in, const float* __restrict__ w,
    const float* __restrict__ bias, float* __restrict__ out,
    int Cin, int Cout, int Hin, int Win, int relu)
{
    __shared__ float s_in[CC][10][10];
    __shared__ float s_w[CC * 16 * 64];

    int Hout = Hin * 2, Wout = Win * 2;
    int coutTiles = Cout >> 6;
    int n     = blockIdx.z / coutTiles;
    int cout0 = (blockIdx.z % coutTiles) << 6;
    int oy0 = blockIdx.y << 4, ox0 = blockIdx.x << 4;
    int tid = threadIdx.x;
    int pg = tid & 15;           // output row 0..15
    int cg4 = (tid >> 4) << 2;   // first of 4 couts (16 groups)

    ull acc2[2][16];
    {
        ull b01 = pack2(bias[cout0 + cg4 + 0], bias[cout0 + cg4 + 1]);
        ull b23 = pack2(bias[cout0 + cg4 + 2], bias[cout0 + cg4 + 3]);
        #pragma unroll
        for (int q = 0; q < 16; q++) { acc2[0][q] = b01; acc2[1][q] = b23; }
    }

    size_t HW = (size_t)Hin * Win;
    const float* in_n = in + (size_t)n * Cin * HW;
    int hbase = (oy0 >> 1) - 1, wbase = (ox0 >> 1) - 1;
    int rp = pg & 1;
    int lh0 = (pg >> 1) + rp;    // local input row = lh0 + a

    #pragma unroll 1
    for (int c0 = 0; c0 < Cin; c0 += CC) {
        // ---- stage input (10x10 region per channel), flattened ----
        for (int i = tid; i < CC * 100; i += 256) {
            int cl = i / 100, rem = i - cl * 100;
            int ry = rem / 10, rx = rem - ry * 10;
            int c = c0 + cl, gy = hbase + ry, gx = wbase + rx;
            bool ok = (c < Cin) && (gy >= 0) && (gy < Hin) && (gx >= 0) && (gx < Win);
            s_in[cl][ry][rx] = ok ? in_n[(size_t)c * HW + (size_t)gy * Win + gx] : 0.f;
        }
        // ---- stage weights ----
        for (int i = tid; i < CC * 16 * 64; i += 256) {
            int tap = i & 15, cl = (i >> 4) & (CC - 1), co = i >> 7;
            int c = c0 + cl;
            float v = (c < Cin) ? w[((size_t)(cout0 + co) * Cin + c) * 16 + tap] : 0.f;
            stw(s_w, cl * 16 + tap, co, v);
        }
        __syncthreads();

        #pragma unroll 1
        for (int cl = 0; cl < CC; cl++) {
            #pragma unroll
            for (int a = 0; a < 2; a++) {
                const float* row = &s_in[cl][lh0 + a][0];
                ull iv[10];
                #pragma unroll
                for (int lx = 0; lx < 10; lx++) iv[lx] = splat2(row[lx]);
                int khrow = cl * 16 + (rp + 2 * a) * 4;
                #pragma unroll
                for (int b = 0; b < 2; b++) {
                    ull we01, we23, wo01, wo23;
                    ldw2x2(s_w, khrow + 2 * b,     cg4, we01, we23); // kw even
                    ldw2x2(s_w, khrow + 2 * b + 1, cg4, wo01, wo23); // kw odd
                    #pragma unroll
                    for (int m = 0; m < 8; m++) {
                        ull se = iv[m + b];        // even col q=2m
                        ull so = iv[m + 1 + b];    // odd  col q=2m+1
                        fma2(acc2[0][2 * m],     we01, se);
                        fma2(acc2[1][2 * m],     we23, se);
                        fma2(acc2[0][2 * m + 1], wo01, so);
                        fma2(acc2[1][2 * m + 1], wo23, so);
                    }
                }
            }
        }
        __syncthreads();
    }

    size_t HWo = (size_t)Hout * Wout;
    float* out_p = out + (size_t)n * Cout * HWo + (size_t)(oy0 + pg) * Wout + ox0;
    float v[4][16];
    #pragma unroll
    for (int jp = 0; jp < 2; jp++)
        #pragma unroll
        for (int q = 0; q < 16; q++) {
            float2 f = unpack2(acc2[jp][q]);
            v[2 * jp][q] = relu ? fmaxf(f.x, 0.f) : f.x;
            v[2 * jp + 1][q] = relu ? fmaxf(f.y, 0.f) : f.y;
        }
    #pragma unroll
    for (int j = 0; j < 4; j++) {
        float* p = out_p + (size_t)(cout0 + cg4 + j) * HWo;
        #pragma unroll
        for (int g = 0; g < 4; g++)
            *(float4*)(p + 4 * g) = make_float4(v[j][4 * g], v[j][4 * g + 1],
                                                v[j][4 * g + 2], v[j][4 * g + 3]);
    }
}

// =====================================================================
// 1x1 conv (proj): Cout=64 tile, 64 pixels per block.
// =====================================================================
__global__ void __launch_bounds__(128) conv1x1(
    const float* __restrict__ in, const float* __restrict__ w,
    const float* __restrict__ bias, float* __restrict__ out,
    int Cin, int Cout, int HW)
{
    __shared__ float s_in[CC * 64];
    __shared__ float s_w[CC * 64];
    int n = blockIdx.y;
    int hw0 = blockIdx.x * 64;
    int tid = threadIdx.x, pg = tid & 7, cg4 = (tid >> 3) << 2;

    ull acc2[2][8];
    {
        ull b01 = pack2(bias[cg4 + 0], bias[cg4 + 1]);
        ull b23 = pack2(bias[cg4 + 2], bias[cg4 + 3]);
        #pragma unroll
        for (int q = 0; q < 8; q++) { acc2[0][q] = b01; acc2[1][q] = b23; }
    }

    #pragma unroll 1
    for (int c0 = 0; c0 < Cin; c0 += CC) {
        for (int i = tid; i < CC * 64; i += 128) {
            int cl = i >> 6, px = i & 63;
            s_in[cl * 64 + px] = in[((size_t)n * Cin + c0 + cl) * HW + hw0 + px];
        }
        for (int i = tid; i < CC * 64; i += 128) {
            int cl = i & 7, co = i >> 3;
            stw(s_w, cl, co, w[(size_t)co * Cin + c0 + cl]);
        }
        __syncthreads();
        #pragma unroll
        for (int cl = 0; cl < CC; cl++) {
            ull w01, w23;
            ldw2x2(s_w, cl, cg4, w01, w23);
            #pragma unroll
            for (int q = 0; q < 8; q++) {
                ull s = splat2(s_in[cl * 64 + pg * 8 + q]);
                fma2(acc2[0][q], w01, s);
                fma2(acc2[1][q], w23, s);
            }
        }
        __syncthreads();
    }
    float v[4][8];
    #pragma unroll
    for (int jp = 0; jp < 2; jp++)
        #pragma unroll
        for (int q = 0; q < 8; q++) {
            float2 f = unpack2(acc2[jp][q]);
            v[2 * jp][q] = f.x; v[2 * jp + 1][q] = f.y;
        }
    #pragma unroll
    for (int j = 0; j < 4; j++) {
        float* p = out + ((size_t)n * Cout + cg4 + j) * HW + hw0 + pg * 8;
        *(float4*)p       = make_float4(v[j][0], v[j][1], v[j][2], v[j][3]);
        *(float4*)(p + 4) = make_float4(v[j][4], v[j][5], v[j][6], v[j][7]);
    }
}

// =====================================================================
// VQ: per (n,h,w) row of z (D=64), argmin over K=1024 codes of |c|^2-2 z.c
// =====================================================================
__global__ void __launch_bounds__(128) vq_kernel(
    const float* __restrict__ z, const float* __restrict__ cb, float* __restrict__ zq)
{
    __shared__ float4 s_cb[128 * 16];
    int row = blockIdx.x * 128 + threadIdx.x;
    int n = row >> 10, hw = row & 1023;
    const float* zp = z + (size_t)n * 64 * 1024 + hw;
    float4 zv[16];
    #pragma unroll
    for (int j = 0; j < 16; j++)
        zv[j] = make_float4(zp[(4 * j + 0) * 1024], zp[(4 * j + 1) * 1024],
                            zp[(4 * j + 2) * 1024], zp[(4 * j + 3) * 1024]);

    float best = 3.4e38f;
    int bidx = 0;
    #pragma unroll 1
    for (int k0 = 0; k0 < 1024; k0 += 128) {
        __syncthreads();
        const float4* cbv = (const float4*)cb + (size_t)k0 * 16;
        for (int i = threadIdx.x; i < 128 * 16; i += 128) s_cb[i] = cbv[i];
        __syncthreads();
        #pragma unroll 1
        for (int k = 0; k < 128; k++) {
            float d0 = 0.f, d1 = 0.f, d2 = 0.f, d3 = 0.f;
            #pragma unroll
            for (int j = 0; j < 16; j++) {
                float4 c = s_cb[k * 16 + j];
                float4 zz = zv[j];
                d0 = fmaf(c.x, fmaf(-2.f, zz.x, c.x), d0);
                d1 = fmaf(c.y, fmaf(-2.f, zz.y, c.y), d1);
                d2 = fmaf(c.z, fmaf(-2.f, zz.z, c.z), d2);
                d3 = fmaf(c.w, fmaf(-2.f, zz.w, c.w), d3);
            }
            float dist = (d0 + d1) + (d2 + d3);
            if (dist < best) { best = dist; bidx = k0 + k; }
        }
    }
    const float4* crow = (const float4*)(cb + (size_t)bidx * 64);
    float* qp = zq + (size_t)n * 64 * 1024 + hw;
    #pragma unroll
    for (int j = 0; j < 16; j++) {
        float4 c = crow[j];
        qp[(4 * j + 0) * 1024] = c.x; qp[(4 * j + 1) * 1024] = c.y;
        qp[(4 * j + 2) * 1024] = c.z; qp[(4 * j + 3) * 1024] = c.w;
    }
}

// =====================================================================
// 3x3 s1 p1 output conv, Cout=3 (no relu).
// =====================================================================
__global__ void __launch_bounds__(256) conv3x3_out(
    const float* __restrict__ in, const float* __restrict__ w,
    const float* __restrict__ bias, float* __restrict__ out,
    int Cin, int H, int W)
{
    __shared__ float s_in[16][18][18];
    __shared__ float s_w3[3 * 128 * 9];
    int n = blockIdx.z;
    int ty = blockIdx.y * 16, tx = blockIdx.x * 16;
    int tid = threadIdx.x, px = tid & 15, py = tid >> 4;

    for (int i = tid; i < 3 * Cin * 9; i += 256) s_w3[i] = w[i];

    float a0 = bias[0], a1 = bias[1], a2 = bias[2];
    size_t HW = (size_t)H * W;
    const float* in_n = in + (size_t)n * Cin * HW;

    #pragma unroll 1
    for (int c0 = 0; c0 < Cin; c0 += 16) {
        __syncthreads();
        for (int i = tid; i < 16 * 18 * 18; i += 256) {
            int cl = i / 324, rem = i - cl * 324;
            int ry = rem / 18, rx = rem - ry * 18;
            int c = c0 + cl, gy = ty - 1 + ry, gx = tx - 1 + rx;
            bool ok = (gy >= 0) && (gy < H) && (gx >= 0) && (gx < W);
            s_in[cl][ry][rx] = ok ? in_n[(size_t)c * HW + (size_t)gy * W + gx] : 0.f;
        }
        __syncthreads();
        #pragma unroll 1
        for (int cl = 0; cl < 16; cl++) {
            int c = c0 + cl;
            float w0[9], w1[9], w2[9];
            #pragma unroll
            for (int t = 0; t < 9; t++) {
                w0[t] = s_w3[(0 * Cin + c) * 9 + t];
                w1[t] = s_w3[(1 * Cin + c) * 9 + t];
                w2[t] = s_w3[(2 * Cin + c) * 9 + t];
            }
            #pragma unroll
            for (int kh = 0; kh < 3; kh++)
                #pragma unroll
                for (int kw = 0; kw < 3; kw++) {
                    float iv = s_in[cl][py + kh][px + kw];
                    a0 = fmaf(w0[kh * 3 + kw], iv, a0);
                    a1 = fmaf(w1[kh * 3 + kw], iv, a1);
                    a2 = fmaf(w2[kh * 3 + kw], iv, a2);
                }
        }
    }
    size_t o = (size_t)n * 3 * HW + (size_t)(ty + py) * W + tx + px;
    out[o] = a0; out[o + HW] = a1; out[o + 2 * HW] = a2;
}

// =====================================================================
extern "C" void kernel_launch(void* const* d_in, const int* in_sizes, int n_in,
                              void* d_out, int out_size)
{
    const float* x       = (const float*)d_in[0];
    const float* enc_w0  = (const float*)d_in[1];
    const float* enc_b0  = (const float*)d_in[2];
    const float* enc_w1  = (const float*)d_in[3];
    const float* enc_b1  = (const float*)d_in[4];
    const float* enc_w2  = (const float*)d_in[5];
    const float* enc_b2  = (const float*)d_in[6];
    const float* proj_w  = (const float*)d_in[7];
    const float* proj_b  = (const float*)d_in[8];
    const float* dec_w0  = (const float*)d_in[9];
    const float* dec_b0  = (const float*)d_in[10];
    const float* dec_w1  = (const float*)d_in[11];
    const float* dec_b1  = (const float*)d_in[12];
    const float* dec_w2  = (const float*)d_in[13];
    const float* dec_b2  = (const float*)d_in[14];
    const float* out_w   = (const float*)d_in[15];
    const float* out_b   = (const float*)d_in[16];
    const float* codebook= (const float*)d_in[17];

    float *h0, *h1, *h2, *d0, *d1, *d2;
    cudaGetSymbolAddress((void**)&h0, g_h0);
    cudaGetSymbolAddress((void**)&h1, g_h1);
    cudaGetSymbolAddress((void**)&h2, g_h2);
    cudaGetSymbolAddress((void**)&d0, g_d0);
    cudaGetSymbolAddress((void**)&d1, g_d1);
    cudaGetSymbolAddress((void**)&d2, g_d2);

    float* out   = (float*)d_out;
    float* recon = out;                          // 16*3*256*256
    float* z     = out + 3145728;                // 16*64*32*32
    float* zq    = z + 1048576;                  // 16*64*32*32

    // encoder
    conv4s2<<<dim3(16, 16, 16 * 2), 128>>>(x,  enc_w0, enc_b0, h0, 3,   128, 256, 256, 128, 128, 1);
    conv4s2<<<dim3(8,  8,  16 * 4), 128>>>(h0, enc_w1, enc_b1, h1, 128, 256, 128, 128, 64,  64,  1);
    conv4s2<<<dim3(4,  4,  16 * 8), 128>>>(h1, enc_w2, enc_b2, h2, 256, 512, 64,  64,  32,  32,  1);
    // proj -> z
    conv1x1<<<dim3(16, 16), 128>>>(h2, proj_w, proj_b, z, 512, 64, 1024);
    // quantize -> z_q
    vq_kernel<<<128, 128>>>(z, codebook, zq);
    // decoder (16x16 output tiles, 256 threads) — grids sized Hout/16 per dim
    convT4s2<<<dim3(4,  4,  16 * 8), 256>>>(zq, dec_w0, dec_b0, d0, 64,  512, 32,  32,  1);
    convT4s2<<<dim3(8,  8,  16 * 4), 256>>>(d0, dec_w1, dec_b1, d1, 512, 256, 64,  64,  1);
    convT4s2<<<dim3(16, 16, 16 * 2), 256>>>(d1, dec_w2, dec_b2, d2, 256, 128, 128, 128, 1);
    // output conv -> recon
    conv3x3_out<<<dim3(16, 16, 16), 256>>>(d2, out_w, out_b, recon, 128, 256, 256);
}